// round 12
// baseline (speedup 1.0000x reference)
#include <cuda_runtime.h>
#include <cuda_bf16.h>
#include <cstdint>

// ---------------------------------------------------------------------------
// CapsuleNetwork forward, 2 kernels:
//  mega : per block (c, 2 conv rows = 40 k):
//          - in-smem conv for its own xf tile (no g_xf round trip)
//          - stream W1[j, 40k, 8m, 32c] (327KB/block), c-reduce -> ws smem
//          - GEMM [64b x 64jm] over 40 k -> deterministic g_part slice
//  final: contiguous 320-slice reduce + squash + digit caps + routing(3)
//  g_part layout [b][kt][jm] so each final block reads 81.9KB contiguous.
// ---------------------------------------------------------------------------

#define B_SZ 64
#define IN_UNITS 12800      // 32*20*20
#define KT 40               // k per tile = 2 rows x 20
#define NKT 320             // 12800 / 40

__device__ float g_part[B_SZ * NKT * 64];    // 5.24 MB [b][kt][jm]

// dynamic smem layout (floats)
#define SM_IMG   0                    // [64][284]  10 rows x 28 + pad
#define SM_XST   18176                // [40][68]   xf tile transposed [kk][b]
#define SM_WS    20896                // [40][68]   wsum tile [kk][jm]
#define SM_WSM   23616                // [82]       conv weights + bias
#define SM_TOTAL 23698                // floats -> 94792 bytes

__global__ __launch_bounds__(512) void mega_kernel(
    const float* __restrict__ x, const float* __restrict__ w,
    const float* __restrict__ bias, const float* __restrict__ W1)
{
    extern __shared__ float sm[];
    float* img = sm + SM_IMG;
    float* xsT = sm + SM_XST;
    float* ws  = sm + SM_WS;
    float* wsm = sm + SM_WSM;

    int bid = blockIdx.x;        // 0..319 ; k0 = bid*40
    int t = threadIdx.x;         // 0..511
    int c = bid / 10;            // conv channel
    int y0 = (bid % 10) * 2;     // first of 2 output rows

    const float4* __restrict__ Wv = (const float4*)W1;
    size_t base0 = (size_t)bid * 2560;          // f4 offset, j=0

    // ---- issue first stream batch early (DRAM busy during conv) ----
    float4 cur[5], nxt[5];
    #pragma unroll
    for (int q = 0; q < 5; q++) cur[q] = Wv[base0 + q * 512 + t];

    // ---- cooperative image rows load: rows y0..y0+9, all 64 b ----
    {
        const float* xb = x + y0 * 28;
        for (int i = t; i < 4480; i += 512) {
            int bb = i / 70, off = (i % 70) * 4;
            *(float4*)&img[bb * 284 + off] = *(const float4*)&xb[bb * 784 + off];
        }
    }
    if (t < 81) wsm[t] = w[c * 81 + t];
    if (t == 81) wsm[81] = bias[c];
    __syncthreads();

    // ---- conv: thread = (b = t>>3, yl = (t>>2)&1, xq = t&3), 5 outputs ----
    {
        int b = t >> 3, yl = (t >> 2) & 1, x0 = (t & 3) * 5;
        float bv = wsm[81];
        float a0 = 0.f, a1 = 0.f, a2 = 0.f, a3 = 0.f, a4 = 0.f;
        const float* ib = &img[b * 284 + yl * 28 + x0];
        #pragma unroll
        for (int i = 0; i < 9; i++) {
            float wr[9];
            #pragma unroll
            for (int jj = 0; jj < 9; jj++) wr[jj] = wsm[i * 9 + jj];
            float xr[13];
            #pragma unroll
            for (int u = 0; u < 13; u++) xr[u] = ib[i * 28 + u];
            #pragma unroll
            for (int jj = 0; jj < 9; jj++) {
                a0 = fmaf(xr[0 + jj], wr[jj], a0);
                a1 = fmaf(xr[1 + jj], wr[jj], a1);
                a2 = fmaf(xr[2 + jj], wr[jj], a2);
                a3 = fmaf(xr[3 + jj], wr[jj], a3);
                a4 = fmaf(xr[4 + jj], wr[jj], a4);
            }
        }
        int kk0 = yl * 20 + x0;
        xsT[(kk0 + 0) * 68 + b] = fmaxf(a0 + bv, 0.f);
        xsT[(kk0 + 1) * 68 + b] = fmaxf(a1 + bv, 0.f);
        xsT[(kk0 + 2) * 68 + b] = fmaxf(a2 + bv, 0.f);
        xsT[(kk0 + 3) * 68 + b] = fmaxf(a3 + bv, 0.f);
        xsT[(kk0 + 4) * 68 + b] = fmaxf(a4 + bv, 0.f);
    }

    // ---- W1 stream, 8 j batches, prefetch-pipelined; c-reduce -> ws ----
    int lanec = t & 7;
    #pragma unroll
    for (int j = 0; j < 8; j++) {
        if (j < 7) {
            size_t nb = base0 + (size_t)(j + 1) * 819200;
            #pragma unroll
            for (int q = 0; q < 5; q++) nxt[q] = Wv[nb + q * 512 + t];
        }
        #pragma unroll
        for (int q = 0; q < 5; q++) {
            float p = (cur[q].x + cur[q].y) + (cur[q].z + cur[q].w);
            p += __shfl_xor_sync(0xffffffffu, p, 1);
            p += __shfl_xor_sync(0xffffffffu, p, 2);
            p += __shfl_xor_sync(0xffffffffu, p, 4);
            if (lanec == 0) {
                int r = (q * 512 + t) >> 3;        // kk*8 + m
                ws[(r >> 3) * 68 + j * 8 + (r & 7)] = p;
            }
        }
        if (j < 7) {
            #pragma unroll
            for (int q = 0; q < 5; q++) cur[q] = nxt[q];
        }
    }
    __syncthreads();

    // ---- GEMM [64b x 64jm] over 40 k ----
    int bq  = t >> 5;     // 0..15 -> b = 4*bq..
    int jm2 = t & 31;     // 0..31 -> jm = 2*jm2..

    float a0 = 0.f, a1 = 0.f, a2 = 0.f, a3 = 0.f;
    float a4 = 0.f, a5 = 0.f, a6 = 0.f, a7 = 0.f;

    #pragma unroll
    for (int kk = 0; kk < KT; kk++) {
        float4 xv = *(const float4*)&xsT[kk * 68 + bq * 4];
        float2 wv = *(const float2*)&ws[kk * 68 + jm2 * 2];
        a0 = fmaf(xv.x, wv.x, a0);
        a1 = fmaf(xv.y, wv.x, a1);
        a2 = fmaf(xv.z, wv.x, a2);
        a3 = fmaf(xv.w, wv.x, a3);
        a4 = fmaf(xv.x, wv.y, a4);
        a5 = fmaf(xv.y, wv.y, a5);
        a6 = fmaf(xv.z, wv.y, a6);
        a7 = fmaf(xv.w, wv.y, a7);
    }

    // g_part layout [b][kt][jm] : index = b*20480 + bid*64 + jm
    int col = jm2 * 2;
    float* dst = &g_part[(size_t)bid * 64 + col];
    dst[(size_t)(bq * 4 + 0) * 20480]     = a0;
    dst[(size_t)(bq * 4 + 1) * 20480]     = a1;
    dst[(size_t)(bq * 4 + 2) * 20480]     = a2;
    dst[(size_t)(bq * 4 + 3) * 20480]     = a3;
    dst[(size_t)(bq * 4 + 0) * 20480 + 1] = a4;
    dst[(size_t)(bq * 4 + 1) * 20480 + 1] = a5;
    dst[(size_t)(bq * 4 + 2) * 20480 + 1] = a6;
    dst[(size_t)(bq * 4 + 3) * 20480 + 1] = a7;
}

// ---------------------------------------------------------------------------
// Kernel 2: final. One block per batch b, 256 threads.
//  - reduce 320 slices from CONTIGUOUS g_part[b]: thread=(s in 16, c4 in 16),
//    20 float4 each, fully coalesced 256B warp segments, MLP 20.
//  - squash -> v1; u2 = W2 v1; routing(3) with smem-dot b-updates.
// ---------------------------------------------------------------------------
__global__ __launch_bounds__(256) void final_kernel(
    const float* __restrict__ W2, float* __restrict__ out)
{
    int b = blockIdx.x;
    int t = threadIdx.x;

    __shared__ float red[16][68];     // [slice][jm]
    __shared__ float ss[64];          // s1
    __shared__ float v1s[64];         // v1
    __shared__ float u2s[80][17];     // u2[j*8+k][m]
    __shared__ float vs[160];         // current v[j][m]
    __shared__ float es[80];          // exp(logits)
    __shared__ float bs_s[80];        // routing logits
    __shared__ float inv_ds[8];       // 1/softmax-denominator per k

    // ---- parallel partial reduction over contiguous [320][64] block ----
    {
        int c4 = t & 15, s = t >> 4;
        const float* src = &g_part[(size_t)b * 20480 + s * 64 + c4 * 4];
        float4 acc = make_float4(0.f, 0.f, 0.f, 0.f);
        #pragma unroll
        for (int q = 0; q < 20; q++) {
            float4 v = *(const float4*)&src[(size_t)q * 1024];   // 16 slices stride
            acc.x += v.x; acc.y += v.y; acc.z += v.z; acc.w += v.w;
        }
        red[s][c4 * 4 + 0] = acc.x;
        red[s][c4 * 4 + 1] = acc.y;
        red[s][c4 * 4 + 2] = acc.z;
        red[s][c4 * 4 + 3] = acc.w;
    }
    __syncthreads();
    if (t < 64) {
        float s = 0.f;
        #pragma unroll
        for (int i = 0; i < 16; i++) s += red[i][t];
        ss[t] = s * 0.125f;
    }
    __syncthreads();
    if (t < 64) {
        int jj = t >> 3;
        float nsq = 0.f;
        #pragma unroll
        for (int mm = 0; mm < 8; mm++) { float v = ss[jj * 8 + mm]; nsq = fmaf(v, v, nsq); }
        float n = sqrtf(nsq);
        v1s[t] = ss[t] * (n / (1.f + nsq));
    }
    if (t < 80) bs_s[t] = 0.f;
    __syncthreads();

    bool act = (t < 160);
    int jraw = t >> 4;
    int j = (jraw < 10) ? jraw : 0;
    int m = t & 15;

    float u2r[8];
    const float4* W2v = (const float4*)W2;
    const float4* v1v = (const float4*)v1s;
    #pragma unroll
    for (int k = 0; k < 8; k++) {
        int base = ((j * 8 + k) * 16 + m) * 2;
        float4 wa = W2v[base], wb = W2v[base + 1];
        float4 va = v1v[k * 2], vb = v1v[k * 2 + 1];
        u2r[k] = wa.x * va.x + wa.y * va.y + wa.z * va.z + wa.w * va.w
               + wb.x * vb.x + wb.y * vb.y + wb.z * vb.z + wb.w * vb.w;
        if (act) u2s[j * 8 + k][m] = u2r[k];
    }
    __syncthreads();

    float v = 0.f;
    for (int it = 0; it < 3; it++) {
        if (t < 80) es[t] = __expf(bs_s[t]);
        __syncthreads();
        if (t < 8) {
            float d = 0.f;
            #pragma unroll
            for (int jj = 0; jj < 10; jj++) d += es[jj * 8 + t];
            inv_ds[t] = 1.f / d;
        }
        __syncthreads();
        float s = 0.f;
        #pragma unroll
        for (int k = 0; k < 8; k++)
            s = fmaf(es[j * 8 + k] * inv_ds[k], u2r[k], s);
        float p = s * s;
        p += __shfl_xor_sync(0xffffffffu, p, 1);
        p += __shfl_xor_sync(0xffffffffu, p, 2);
        p += __shfl_xor_sync(0xffffffffu, p, 4);
        p += __shfl_xor_sync(0xffffffffu, p, 8);
        float n = sqrtf(p);
        v = s * (n / (1.f + p));
        if (act) vs[t] = v;
        __syncthreads();
        if (it < 2) {
            if (t < 80) {
                const float* uv = u2s[t];
                const float* vv = &vs[(t >> 3) * 16];
                float q = 0.f;
                #pragma unroll
                for (int mm = 0; mm < 16; mm++) q = fmaf(uv[mm], vv[mm], q);
                bs_s[t] += q;
            }
            __syncthreads();
        }
    }

    if (act) out[b * 160 + t] = v;
}

// ---------------------------------------------------------------------------
extern "C" void kernel_launch(void* const* d_in, const int* in_sizes, int n_in,
                              void* d_out, int out_size)
{
    const float* x      = (const float*)d_in[0];  // [64,1,28,28]
    const float* conv_w = (const float*)d_in[1];  // [32,1,9,9]
    const float* conv_b = (const float*)d_in[2];  // [32]
    const float* W1     = (const float*)d_in[3];  // [8,12800,8,32]
    const float* W2     = (const float*)d_in[4];  // [10,8,16,8]
    float* out = (float*)d_out;                   // [64,10,16]

    cudaFuncSetAttribute(mega_kernel,
                         cudaFuncAttributeMaxDynamicSharedMemorySize,
                         SM_TOTAL * 4);

    mega_kernel<<<NKT, 512, SM_TOTAL * 4>>>(x, conv_w, conv_b, W1);
    final_kernel<<<B_SZ, 256>>>(W2, out);
}